// round 16
// baseline (speedup 1.0000x reference)
#include <cuda_runtime.h>
#include <cuda_fp16.h>
#include <cstdint>

#define N_NODES 50000
#define N_EDGES 800000
#define FEAT    1024
#define EMB     128

// ---------------------------------------------------------------------------
// Device-global scratch
// ---------------------------------------------------------------------------
__device__ float  g_h[(size_t)N_NODES * EMB];     // h accumulator (25.6 MB)
__device__ __half g_wh16[(size_t)EMB * FEAT];     // W split hi (fp16)
__device__ __half g_wl16[(size_t)EMB * FEAT];     // W split lo (fp16)
__device__ int    g_cnt[N_NODES];                 // degree counters
__device__ int    g_off[N_NODES + 1];             // CSR offsets
__device__ int    g_part[128];                    // scan partials
__device__ int2   g_edge[N_EDGES];                // bucketed (col, val-bits)

// ---------------------------------------------------------------------------
// helpers
// ---------------------------------------------------------------------------
__device__ __forceinline__ void split16(float v, __half& hi, __half& lo) {
    hi = __float2half_rn(v);
    lo = __float2half_rn(v - __half2float(hi));
}

__device__ __forceinline__ void mma16(float d[4], const uint32_t a[4],
                                      uint32_t b0, uint32_t b1) {
    asm volatile(
        "mma.sync.aligned.m16n8k16.row.col.f32.f16.f16.f32 "
        "{%0,%1,%2,%3}, {%4,%5,%6,%7}, {%8,%9}, {%0,%1,%2,%3};"
        : "+f"(d[0]), "+f"(d[1]), "+f"(d[2]), "+f"(d[3])
        : "r"(a[0]), "r"(a[1]), "r"(a[2]), "r"(a[3]), "r"(b0), "r"(b1));
}

// ---------------------------------------------------------------------------
// split W once into fp16 hi/lo
// ---------------------------------------------------------------------------
__global__ void split_w_kernel(const float* __restrict__ w) {
    int i = blockIdx.x * blockDim.x + threadIdx.x;
    if (i < EMB * FEAT) {
        __half h, l;
        split16(w[i], h, l);
        g_wh16[i] = h;
        g_wl16[i] = l;
    }
}

// ---------------------------------------------------------------------------
// GEMM: h += x[:, khalf] @ W[:, khalf]^T  (K-split 2, g_h pre-zeroed).
// Double-buffered smem ring, ONE __syncthreads per iteration:
//   it: store(chunk it+1 -> buf s^1); LDG(it+2 -> regs); MMA(buf s); sync
// Inner MMA body = champion scalar-LDS pattern verbatim. occ=2 enforced.
// ---------------------------------------------------------------------------
#define SH  40                         // half row stride (conflict-free)
#define KC  32
#define KHALF 512
#define NKIT (KHALF / KC)              // 16
#define TILE_H (128 * SH)              // 5120 halves per tile
#define SMEMB  (2 * 3 * TILE_H * 2)    // 2 stages x 3 tiles = 61440 B

__global__ __launch_bounds__(256, 2)
void gemm_fp16_mma(const float* __restrict__ x) {
    extern __shared__ __half dsm[];

    const int tid  = threadIdx.x;
    const int mt   = blockIdx.x >> 1;
    const int kb   = (blockIdx.x & 1) * KHALF;
    const int m0   = mt * 128;
    const int wid  = tid >> 5;
    const int lane = tid & 31;
    const int wm   = (wid & 3) * 32;    // warp M offset
    const int wn   = (wid >> 2) * 64;   // warp N offset
    const int g    = lane >> 2;
    const int t    = lane & 3;

    const int lrow = tid >> 1;
    const int lk   = (tid & 1) * 16;
    const int gxr  = m0 + lrow;
    const bool xok = (gxr < N_NODES);
    const float* xrow = x + (size_t)(xok ? gxr : 0) * FEAT + kb;
    const __half* whrow = g_wh16 + (size_t)lrow * FEAT + kb;
    const __half* wlrow = g_wl16 + (size_t)lrow * FEAT + kb;

    float acc[2][8][4];
#pragma unroll
    for (int mi = 0; mi < 2; mi++)
#pragma unroll
        for (int ni = 0; ni < 8; ni++)
#pragma unroll
            for (int j = 0; j < 4; j++) acc[mi][ni][j] = 0.f;

    float4 xb[4];
    uint4  whb[2], wlb[2];

    // register -> smem store of the currently-buffered chunk
    auto store_chunk = [&](int stage) {
        __half* base = dsm + stage * 3 * TILE_H;
        __half h[16];
        const float* xf = (const float*)xb;
#pragma unroll
        for (int j = 0; j < 16; j++) h[j] = __float2half_rn(xf[j]);
        __half* pxh = base + lrow * SH + lk;
        *(uint4*)(pxh)     = *(const uint4*)(h);
        *(uint4*)(pxh + 8) = *(const uint4*)(h + 8);
        __half* pwh = base + TILE_H + lrow * SH + lk;
        __half* pwl = base + 2 * TILE_H + lrow * SH + lk;
        *(uint4*)(pwh)     = whb[0];
        *(uint4*)(pwh + 8) = whb[1];
        *(uint4*)(pwl)     = wlb[0];
        *(uint4*)(pwl + 8) = wlb[1];
    };
    auto load_chunk = [&](int it) {
        const int k0 = it * KC;
#pragma unroll
        for (int j = 0; j < 4; j++)
            xb[j] = xok ? *(const float4*)(xrow + k0 + lk + j * 4)
                        : make_float4(0.f, 0.f, 0.f, 0.f);
        whb[0] = *(const uint4*)(whrow + k0 + lk);
        whb[1] = *(const uint4*)(whrow + k0 + lk + 8);
        wlb[0] = *(const uint4*)(wlrow + k0 + lk);
        wlb[1] = *(const uint4*)(wlrow + k0 + lk + 8);
    };

    // ---- prologue: chunk0 -> buf0; prefetch chunk1 into regs ----
    load_chunk(0);
    store_chunk(0);
    load_chunk(1);
    __syncthreads();

    for (int it = 0; it < NKIT; ++it) {
        const int s = it & 1;

        // store chunk it+1 into the other buffer (safe: its readers finished
        // at the sync ending iteration it-1), then prefetch chunk it+2.
        if (it + 1 < NKIT) {
            store_chunk(s ^ 1);
            if (it + 2 < NKIT) load_chunk(it + 2);
        }

        // ---- MMAs on buffer s (champion scalar-LDS pattern) ----
        const __half* axh = dsm + s * 3 * TILE_H;
        const __half* swh = axh + TILE_H;
        const __half* swl = axh + 2 * TILE_H;
#pragma unroll
        for (int ks = 0; ks < 2; ks++) {
            const int k0 = ks * 16;
            uint32_t ah[2][4];
#pragma unroll
            for (int mi = 0; mi < 2; mi++) {
                const int r = wm + mi * 16;
                const __half* bh = axh + k0 + 2 * t;
                ah[mi][0] = *(const uint32_t*)(bh + (r + g)     * SH);
                ah[mi][1] = *(const uint32_t*)(bh + (r + g + 8) * SH);
                ah[mi][2] = *(const uint32_t*)(bh + (r + g)     * SH + 8);
                ah[mi][3] = *(const uint32_t*)(bh + (r + g + 8) * SH + 8);
            }
#pragma unroll
            for (int ni = 0; ni < 8; ni++) {
                const int n = wn + ni * 8 + g;
                uint32_t bh0 = *(const uint32_t*)(swh + n * SH + k0 + 2 * t);
                uint32_t bh1 = *(const uint32_t*)(swh + n * SH + k0 + 2 * t + 8);
                uint32_t bl0 = *(const uint32_t*)(swl + n * SH + k0 + 2 * t);
                uint32_t bl1 = *(const uint32_t*)(swl + n * SH + k0 + 2 * t + 8);
#pragma unroll
                for (int mi = 0; mi < 2; mi++) {
                    mma16(acc[mi][ni], ah[mi], bh0, bh1);   // xh*wh
                    mma16(acc[mi][ni], ah[mi], bl0, bl1);   // xh*wl
                }
            }
        }
        __syncthreads();   // one barrier per iteration
    }

    // epilogue: accumulate this K-half into g_h (pre-zeroed)
#pragma unroll
    for (int mi = 0; mi < 2; mi++) {
#pragma unroll
        for (int ni = 0; ni < 8; ni++) {
            const int r = m0 + wm + mi * 16 + g;
            const int c = wn + ni * 8 + 2 * t;
            if (r < N_NODES) {
                float* dst = g_h + (size_t)r * EMB + c;
                asm volatile("red.global.add.v2.f32 [%0], {%1,%2};"
                             :: "l"(dst), "f"(acc[mi][ni][0]),
                                "f"(acc[mi][ni][1]) : "memory");
            }
            if (r + 8 < N_NODES) {
                float* dst = g_h + (size_t)(r + 8) * EMB + c;
                asm volatile("red.global.add.v2.f32 [%0], {%1,%2};"
                             :: "l"(dst), "f"(acc[mi][ni][2]),
                                "f"(acc[mi][ni][3]) : "memory");
            }
        }
    }
}

// ---------------------------------------------------------------------------
// CSR build: memset(g_cnt) -> hist -> scan x3 -> bucket
// ---------------------------------------------------------------------------
__global__ void hist_kernel(const int* __restrict__ row) {
    int e = blockIdx.x * blockDim.x + threadIdx.x;
    if (e < N_EDGES) atomicAdd(&g_cnt[row[e]], 1);
}

#define SCAN_B 512
#define SCAN_NB ((N_NODES + SCAN_B - 1) / SCAN_B)   // 98

__global__ void scan1_kernel() {
    __shared__ int s[SCAN_B];
    int i = blockIdx.x * SCAN_B + threadIdx.x;
    int v = (i < N_NODES) ? g_cnt[i] : 0;
    s[threadIdx.x] = v;
    __syncthreads();
#pragma unroll
    for (int d = 1; d < SCAN_B; d <<= 1) {
        int tmp = (threadIdx.x >= d) ? s[threadIdx.x - d] : 0;
        __syncthreads();
        s[threadIdx.x] += tmp;
        __syncthreads();
    }
    if (i < N_NODES) g_off[i] = s[threadIdx.x] - v;
    if (threadIdx.x == SCAN_B - 1) g_part[blockIdx.x] = s[SCAN_B - 1];
}

__global__ void scan2_kernel() {
    __shared__ int s[128];
    int tid = threadIdx.x;
    int v = (tid < SCAN_NB) ? g_part[tid] : 0;
    s[tid] = v;
    __syncthreads();
#pragma unroll
    for (int d = 1; d < 128; d <<= 1) {
        int tmp = (tid >= d) ? s[tid - d] : 0;
        __syncthreads();
        s[tid] += tmp;
        __syncthreads();
    }
    if (tid < SCAN_NB) g_part[tid] = s[tid] - v;
    if (tid == 0) g_off[N_NODES] = N_EDGES;
}

__global__ void scan3_kernel() {
    int i = blockIdx.x * SCAN_B + threadIdx.x;
    if (i < N_NODES) {
        g_off[i] += g_part[blockIdx.x];
        g_cnt[i] = 0;
    }
}

__global__ void bucket_kernel(const int* __restrict__ row,
                              const int* __restrict__ col,
                              const float* __restrict__ vals) {
    int e = blockIdx.x * blockDim.x + threadIdx.x;
    if (e < N_EDGES) {
        int r = row[e];
        int pos = g_off[r] + atomicAdd(&g_cnt[r], 1);
        g_edge[pos] = make_int2(col[e], __float_as_int(vals[e]));
    }
}

// ---------------------------------------------------------------------------
// Gather: one warp per destination node; atomic-free, writes out once.
// ---------------------------------------------------------------------------
__global__ void gather_kernel(float* __restrict__ out) {
    const int lane = threadIdx.x & 31;
    const int node = (blockIdx.x * blockDim.x + threadIdx.x) >> 5;
    if (node >= N_NODES) return;

    const int beg = g_off[node];
    const int end = g_off[node + 1];

    float4 acc = make_float4(0.f, 0.f, 0.f, 0.f);
    for (int e = beg; e < end; e++) {
        const int2 ev = g_edge[e];
        const float v = __int_as_float(ev.y);
        const float4 hv = __ldg((const float4*)(g_h + (size_t)ev.x * EMB) + lane);
        acc.x = fmaf(v, hv.x, acc.x);
        acc.y = fmaf(v, hv.y, acc.y);
        acc.z = fmaf(v, hv.z, acc.z);
        acc.w = fmaf(v, hv.w, acc.w);
    }
    *((float4*)(out + (size_t)node * EMB) + lane) = acc;
}

// ---------------------------------------------------------------------------
// Launch (R15 structure). GEMM stays launch #6 for the ncu window.
// ---------------------------------------------------------------------------
extern "C" void kernel_launch(void* const* d_in, const int* in_sizes, int n_in,
                              void* d_out, int out_size) {
    const float* x    = (const float*)d_in[0];
    const float* w    = (const float*)d_in[1];
    const int*   row  = (const int*)  d_in[2];
    const int*   col  = (const int*)  d_in[3];
    const float* vals = (const float*)d_in[4];
    float*       out  = (float*)d_out;

    static cudaStream_t s_side = nullptr;
    static cudaEvent_t  ev_fork = nullptr, ev_join = nullptr, ev_hzero = nullptr;
    static bool attr_set = false;
    if (s_side == nullptr) {
        cudaStreamCreateWithFlags(&s_side, cudaStreamNonBlocking);
        cudaEventCreateWithFlags(&ev_fork,  cudaEventDisableTiming);
        cudaEventCreateWithFlags(&ev_join,  cudaEventDisableTiming);
        cudaEventCreateWithFlags(&ev_hzero, cudaEventDisableTiming);
    }
    if (!attr_set) {
        cudaFuncSetAttribute(gemm_fp16_mma,
                             cudaFuncAttributeMaxDynamicSharedMemorySize, SMEMB);
        attr_set = true;
    }

    int*   cnt_ptr = nullptr;
    float* h_ptr   = nullptr;
    cudaGetSymbolAddress((void**)&cnt_ptr, g_cnt);
    cudaGetSymbolAddress((void**)&h_ptr,   g_h);

    // (1) main: split W
    split_w_kernel<<<(EMB * FEAT + 255) / 256, 256>>>(w);

    // fork side stream
    cudaEventRecord(ev_fork, 0);
    cudaStreamWaitEvent(s_side, ev_fork, 0);

    // (2) side: zero h accumulator (GEMM red-epilogue needs it)
    cudaMemsetAsync(h_ptr, 0, (size_t)N_NODES * EMB * sizeof(float), s_side);
    cudaEventRecord(ev_hzero, s_side);
    // (3-5) side: CSR build starts
    cudaMemsetAsync(cnt_ptr, 0, N_NODES * sizeof(int), s_side);
    hist_kernel<<<(N_EDGES + 255) / 256, 256, 0, s_side>>>(row);
    scan1_kernel<<<SCAN_NB, SCAN_B, 0, s_side>>>();

    // (6) main: GEMM (K-split 2, double-buffered, 1 sync/iter) <-- ncu window
    cudaStreamWaitEvent(0, ev_hzero, 0);
    gemm_fp16_mma<<<((N_NODES + 127) / 128) * 2, 256, SMEMB>>>(x);

    // side: finish CSR build
    scan2_kernel<<<1, 128, 0, s_side>>>();
    scan3_kernel<<<SCAN_NB, SCAN_B, 0, s_side>>>();
    bucket_kernel<<<(N_EDGES + 255) / 256, 256, 0, s_side>>>(row, col, vals);
    cudaEventRecord(ev_join, s_side);

    // join, then gather
    cudaStreamWaitEvent(0, ev_join, 0);
    gather_kernel<<<(N_NODES * 32 + 255) / 256, 256>>>(out);
}

// round 17
// speedup vs baseline: 1.0585x; 1.0585x over previous
#include <cuda_runtime.h>
#include <cuda_fp16.h>
#include <cstdint>

#define N_NODES 50000
#define N_EDGES 800000
#define FEAT    1024
#define EMB     128

// ---------------------------------------------------------------------------
// Device-global scratch
// ---------------------------------------------------------------------------
__device__ __half g_h16[(size_t)N_NODES * EMB];   // h accumulator, fp16 (12.8 MB)
__device__ __half g_wh16[(size_t)EMB * FEAT];     // W split hi (fp16)
__device__ __half g_wl16[(size_t)EMB * FEAT];     // W split lo (fp16)
__device__ int    g_cnt[N_NODES];                 // degree counters
__device__ int    g_off[N_NODES + 1];             // CSR offsets
__device__ int    g_part[128];                    // scan partials
__device__ int2   g_edge[N_EDGES];                // bucketed (col, val-bits)

// ---------------------------------------------------------------------------
// helpers
// ---------------------------------------------------------------------------
__device__ __forceinline__ void split16(float v, __half& hi, __half& lo) {
    hi = __float2half_rn(v);
    lo = __float2half_rn(v - __half2float(hi));
}

__device__ __forceinline__ void mma16(float d[4], const uint32_t a[4],
                                      uint32_t b0, uint32_t b1) {
    asm volatile(
        "mma.sync.aligned.m16n8k16.row.col.f32.f16.f16.f32 "
        "{%0,%1,%2,%3}, {%4,%5,%6,%7}, {%8,%9}, {%0,%1,%2,%3};"
        : "+f"(d[0]), "+f"(d[1]), "+f"(d[2]), "+f"(d[3])
        : "r"(a[0]), "r"(a[1]), "r"(a[2]), "r"(a[3]), "r"(b0), "r"(b1));
}

__device__ __forceinline__ void red_h16x2(__half* dst, float a, float b) {
    __half2 hv = __floats2half2_rn(a, b);
    asm volatile("red.global.add.noftz.f16x2 [%0], %1;"
                 :: "l"(dst), "r"(*(const uint32_t*)&hv) : "memory");
}

// ---------------------------------------------------------------------------
// split W once into fp16 hi/lo
// ---------------------------------------------------------------------------
__global__ void split_w_kernel(const float* __restrict__ w) {
    int i = blockIdx.x * blockDim.x + threadIdx.x;
    if (i < EMB * FEAT) {
        __half h, l;
        split16(w[i], h, l);
        g_wh16[i] = h;
        g_wl16[i] = l;
    }
}

// ---------------------------------------------------------------------------
// GEMM: h16 += x[:, khalf] @ W[:, khalf]^T  (K-split 2, g_h16 pre-zeroed).
// R16 double-buffered champion loop; epilogue reduces fp16x2 into g_h16.
// ---------------------------------------------------------------------------
#define SH  40                         // half row stride (conflict-free)
#define KC  32
#define KHALF 512
#define NKIT (KHALF / KC)              // 16
#define TILE_H (128 * SH)              // 5120 halves per tile
#define SMEMB  (2 * 3 * TILE_H * 2)    // 61440 B

__global__ __launch_bounds__(256, 2)
void gemm_fp16_mma(const float* __restrict__ x) {
    extern __shared__ __half dsm[];

    const int tid  = threadIdx.x;
    const int mt   = blockIdx.x >> 1;
    const int kb   = (blockIdx.x & 1) * KHALF;
    const int m0   = mt * 128;
    const int wid  = tid >> 5;
    const int lane = tid & 31;
    const int wm   = (wid & 3) * 32;    // warp M offset
    const int wn   = (wid >> 2) * 64;   // warp N offset
    const int g    = lane >> 2;
    const int t    = lane & 3;

    const int lrow = tid >> 1;
    const int lk   = (tid & 1) * 16;
    const int gxr  = m0 + lrow;
    const bool xok = (gxr < N_NODES);
    const float* xrow = x + (size_t)(xok ? gxr : 0) * FEAT + kb;
    const __half* whrow = g_wh16 + (size_t)lrow * FEAT + kb;
    const __half* wlrow = g_wl16 + (size_t)lrow * FEAT + kb;

    float acc[2][8][4];
#pragma unroll
    for (int mi = 0; mi < 2; mi++)
#pragma unroll
        for (int ni = 0; ni < 8; ni++)
#pragma unroll
            for (int j = 0; j < 4; j++) acc[mi][ni][j] = 0.f;

    float4 xb[4];
    uint4  whb[2], wlb[2];

    auto store_chunk = [&](int stage) {
        __half* base = dsm + stage * 3 * TILE_H;
        __half h[16];
        const float* xf = (const float*)xb;
#pragma unroll
        for (int j = 0; j < 16; j++) h[j] = __float2half_rn(xf[j]);
        __half* pxh = base + lrow * SH + lk;
        *(uint4*)(pxh)     = *(const uint4*)(h);
        *(uint4*)(pxh + 8) = *(const uint4*)(h + 8);
        __half* pwh = base + TILE_H + lrow * SH + lk;
        __half* pwl = base + 2 * TILE_H + lrow * SH + lk;
        *(uint4*)(pwh)     = whb[0];
        *(uint4*)(pwh + 8) = whb[1];
        *(uint4*)(pwl)     = wlb[0];
        *(uint4*)(pwl + 8) = wlb[1];
    };
    auto load_chunk = [&](int it) {
        const int k0 = it * KC;
#pragma unroll
        for (int j = 0; j < 4; j++)
            xb[j] = xok ? *(const float4*)(xrow + k0 + lk + j * 4)
                        : make_float4(0.f, 0.f, 0.f, 0.f);
        whb[0] = *(const uint4*)(whrow + k0 + lk);
        whb[1] = *(const uint4*)(whrow + k0 + lk + 8);
        wlb[0] = *(const uint4*)(wlrow + k0 + lk);
        wlb[1] = *(const uint4*)(wlrow + k0 + lk + 8);
    };

    // ---- prologue ----
    load_chunk(0);
    store_chunk(0);
    load_chunk(1);
    __syncthreads();

    for (int it = 0; it < NKIT; ++it) {
        const int s = it & 1;

        if (it + 1 < NKIT) {
            store_chunk(s ^ 1);
            if (it + 2 < NKIT) load_chunk(it + 2);
        }

        const __half* axh = dsm + s * 3 * TILE_H;
        const __half* swh = axh + TILE_H;
        const __half* swl = axh + 2 * TILE_H;
#pragma unroll
        for (int ks = 0; ks < 2; ks++) {
            const int k0 = ks * 16;
            uint32_t ah[2][4];
#pragma unroll
            for (int mi = 0; mi < 2; mi++) {
                const int r = wm + mi * 16;
                const __half* bh = axh + k0 + 2 * t;
                ah[mi][0] = *(const uint32_t*)(bh + (r + g)     * SH);
                ah[mi][1] = *(const uint32_t*)(bh + (r + g + 8) * SH);
                ah[mi][2] = *(const uint32_t*)(bh + (r + g)     * SH + 8);
                ah[mi][3] = *(const uint32_t*)(bh + (r + g + 8) * SH + 8);
            }
#pragma unroll
            for (int ni = 0; ni < 8; ni++) {
                const int n = wn + ni * 8 + g;
                uint32_t bh0 = *(const uint32_t*)(swh + n * SH + k0 + 2 * t);
                uint32_t bh1 = *(const uint32_t*)(swh + n * SH + k0 + 2 * t + 8);
                uint32_t bl0 = *(const uint32_t*)(swl + n * SH + k0 + 2 * t);
                uint32_t bl1 = *(const uint32_t*)(swl + n * SH + k0 + 2 * t + 8);
#pragma unroll
                for (int mi = 0; mi < 2; mi++) {
                    mma16(acc[mi][ni], ah[mi], bh0, bh1);   // xh*wh
                    mma16(acc[mi][ni], ah[mi], bl0, bl1);   // xh*wl
                }
            }
        }
        __syncthreads();
    }

    // epilogue: accumulate this K-half into fp16 h (pre-zeroed)
#pragma unroll
    for (int mi = 0; mi < 2; mi++) {
#pragma unroll
        for (int ni = 0; ni < 8; ni++) {
            const int r = m0 + wm + mi * 16 + g;
            const int c = wn + ni * 8 + 2 * t;
            if (r < N_NODES)
                red_h16x2(g_h16 + (size_t)r * EMB + c,
                          acc[mi][ni][0], acc[mi][ni][1]);
            if (r + 8 < N_NODES)
                red_h16x2(g_h16 + (size_t)(r + 8) * EMB + c,
                          acc[mi][ni][2], acc[mi][ni][3]);
        }
    }
}

// ---------------------------------------------------------------------------
// CSR build: memset(g_cnt) -> hist -> scan x3 -> bucket
// ---------------------------------------------------------------------------
__global__ void hist_kernel(const int* __restrict__ row) {
    int e = blockIdx.x * blockDim.x + threadIdx.x;
    if (e < N_EDGES) atomicAdd(&g_cnt[row[e]], 1);
}

#define SCAN_B 512
#define SCAN_NB ((N_NODES + SCAN_B - 1) / SCAN_B)   // 98

__global__ void scan1_kernel() {
    __shared__ int s[SCAN_B];
    int i = blockIdx.x * SCAN_B + threadIdx.x;
    int v = (i < N_NODES) ? g_cnt[i] : 0;
    s[threadIdx.x] = v;
    __syncthreads();
#pragma unroll
    for (int d = 1; d < SCAN_B; d <<= 1) {
        int tmp = (threadIdx.x >= d) ? s[threadIdx.x - d] : 0;
        __syncthreads();
        s[threadIdx.x] += tmp;
        __syncthreads();
    }
    if (i < N_NODES) g_off[i] = s[threadIdx.x] - v;
    if (threadIdx.x == SCAN_B - 1) g_part[blockIdx.x] = s[SCAN_B - 1];
}

__global__ void scan2_kernel() {
    __shared__ int s[128];
    int tid = threadIdx.x;
    int v = (tid < SCAN_NB) ? g_part[tid] : 0;
    s[tid] = v;
    __syncthreads();
#pragma unroll
    for (int d = 1; d < 128; d <<= 1) {
        int tmp = (tid >= d) ? s[tid - d] : 0;
        __syncthreads();
        s[tid] += tmp;
        __syncthreads();
    }
    if (tid < SCAN_NB) g_part[tid] = s[tid] - v;
    if (tid == 0) g_off[N_NODES] = N_EDGES;
}

__global__ void scan3_kernel() {
    int i = blockIdx.x * SCAN_B + threadIdx.x;
    if (i < N_NODES) {
        g_off[i] += g_part[blockIdx.x];
        g_cnt[i] = 0;
    }
}

__global__ void bucket_kernel(const int* __restrict__ row,
                              const int* __restrict__ col,
                              const float* __restrict__ vals) {
    int e = blockIdx.x * blockDim.x + threadIdx.x;
    if (e < N_EDGES) {
        int r = row[e];
        int pos = g_off[r] + atomicAdd(&g_cnt[r], 1);
        g_edge[pos] = make_int2(col[e], __float_as_int(vals[e]));
    }
}

// ---------------------------------------------------------------------------
// Gather: one warp per destination node; h in fp16 -> 256B per edge (half
// the L2 traffic of fp32). FMA in fp32; out written fp32 once.
// ---------------------------------------------------------------------------
__global__ void gather_kernel(float* __restrict__ out) {
    const int lane = threadIdx.x & 31;
    const int node = (blockIdx.x * blockDim.x + threadIdx.x) >> 5;
    if (node >= N_NODES) return;

    const int beg = g_off[node];
    const int end = g_off[node + 1];

    float4 acc = make_float4(0.f, 0.f, 0.f, 0.f);
    for (int e = beg; e < end; e++) {
        const int2 ev = g_edge[e];
        const float v = __int_as_float(ev.y);
        // 4 halves per lane (lane covers cols lane*4 .. lane*4+3)
        const uint2 hu = __ldg((const uint2*)(g_h16 + (size_t)ev.x * EMB) + lane);
        const __half2 h01 = *(const __half2*)&hu.x;
        const __half2 h23 = *(const __half2*)&hu.y;
        const float2 f01 = __half22float2(h01);
        const float2 f23 = __half22float2(h23);
        acc.x = fmaf(v, f01.x, acc.x);
        acc.y = fmaf(v, f01.y, acc.y);
        acc.z = fmaf(v, f23.x, acc.z);
        acc.w = fmaf(v, f23.y, acc.w);
    }
    *((float4*)(out + (size_t)node * EMB) + lane) = acc;
}

// ---------------------------------------------------------------------------
// Launch (R16 structure). GEMM stays launch #6 for the ncu window.
// ---------------------------------------------------------------------------
extern "C" void kernel_launch(void* const* d_in, const int* in_sizes, int n_in,
                              void* d_out, int out_size) {
    const float* x    = (const float*)d_in[0];
    const float* w    = (const float*)d_in[1];
    const int*   row  = (const int*)  d_in[2];
    const int*   col  = (const int*)  d_in[3];
    const float* vals = (const float*)d_in[4];
    float*       out  = (float*)d_out;

    static cudaStream_t s_side = nullptr;
    static cudaEvent_t  ev_fork = nullptr, ev_join = nullptr, ev_hzero = nullptr;
    static bool attr_set = false;
    if (s_side == nullptr) {
        cudaStreamCreateWithFlags(&s_side, cudaStreamNonBlocking);
        cudaEventCreateWithFlags(&ev_fork,  cudaEventDisableTiming);
        cudaEventCreateWithFlags(&ev_join,  cudaEventDisableTiming);
        cudaEventCreateWithFlags(&ev_hzero, cudaEventDisableTiming);
    }
    if (!attr_set) {
        cudaFuncSetAttribute(gemm_fp16_mma,
                             cudaFuncAttributeMaxDynamicSharedMemorySize, SMEMB);
        attr_set = true;
    }

    int*    cnt_ptr = nullptr;
    __half* h_ptr   = nullptr;
    cudaGetSymbolAddress((void**)&cnt_ptr, g_cnt);
    cudaGetSymbolAddress((void**)&h_ptr,   g_h16);

    // (1) main: split W
    split_w_kernel<<<(EMB * FEAT + 255) / 256, 256>>>(w);

    // fork side stream
    cudaEventRecord(ev_fork, 0);
    cudaStreamWaitEvent(s_side, ev_fork, 0);

    // (2) side: zero fp16 h accumulator (0x0000 == +0.0h)
    cudaMemsetAsync(h_ptr, 0, (size_t)N_NODES * EMB * sizeof(__half), s_side);
    cudaEventRecord(ev_hzero, s_side);
    // (3-5) side: CSR build
    cudaMemsetAsync(cnt_ptr, 0, N_NODES * sizeof(int), s_side);
    hist_kernel<<<(N_EDGES + 255) / 256, 256, 0, s_side>>>(row);
    scan1_kernel<<<SCAN_NB, SCAN_B, 0, s_side>>>();

    // (6) main: GEMM  <-- ncu window
    cudaStreamWaitEvent(0, ev_hzero, 0);
    gemm_fp16_mma<<<((N_NODES + 127) / 128) * 2, 256, SMEMB>>>(x);

    // side: finish CSR build
    scan2_kernel<<<1, 128, 0, s_side>>>();
    scan3_kernel<<<SCAN_NB, SCAN_B, 0, s_side>>>();
    bucket_kernel<<<(N_EDGES + 255) / 256, 256, 0, s_side>>>(row, col, vals);
    cudaEventRecord(ev_join, s_side);

    // join, then gather (fp16 h: half the L2 bytes)
    cudaStreamWaitEvent(0, ev_join, 0);
    gather_kernel<<<(N_NODES * 32 + 255) / 256, 256>>>(out);
}